// round 3
// baseline (speedup 1.0000x reference)
#include <cuda_runtime.h>
#include <math.h>

#define EDIM 8192      // N == E == 8192
#define TM   128       // rows per CTA
#define TK   64        // K-chunk
#define NTH  256
#define NCHUNK (EDIM / TK)

// ---- shared memory layout (bytes) ----
#define OFF_ADJ0 0          // 32 KB int32 adjacency chunk, buf 0
#define OFF_ADJ1 32768      // buf 1
#define OFF_X0   65536      // 16 KB X chunk, buf 0
#define OFF_X1   81920      // buf 1
#define OFF_BV0  98304      // 768 B: b[64], eb[64], eb2[64]
#define OFF_BV1  99072
#define OFF_P    99840      // 32 KB P tile [TK][TM]
#define OFF_ROWS 132608     // 1.5 KB: a[128], ea[128], ea2[128]
#define OFF_ZC   134144     // 1 KB: z[128], cnt[128]
#define SMEM_BYTES 135168
// epilogue reuse of the front of smem
#define OFF_M    0          // means, stride 65 floats (conflict-free column reads)
#define MSTRIDE  65
#define OFF_W    33280      // 16 KB weight matrix

// ---- device scratch (no mallocs allowed) ----
__device__ __align__(16) float g_q[256];          // 4 x 64 folded W@p vectors
__device__ __align__(16) float g_rA  [2][EDIM];   // per-row score (side 0: a_self, side 1: b_self)
__device__ __align__(16) float g_rEA [2][EDIM];   // exp(row)
__device__ __align__(16) float g_rEA2[2][EDIM];   // exp(0.01*row)
__device__ __align__(16) float g_cB  [2][EDIM];   // per-col score (side 0: a_nb, side 1: b_nb)
__device__ __align__(16) float g_cEB [2][EDIM];
__device__ __align__(16) float g_cEB2[2][EDIM];

__device__ __forceinline__ void cp16(void* dst, const void* src) {
  unsigned sa = (unsigned)__cvta_generic_to_shared(dst);
  asm volatile("cp.async.cg.shared.global [%0], [%1], 16;" :: "r"(sa), "l"(src) : "memory");
}
__device__ __forceinline__ void cp_commit() { asm volatile("cp.async.commit_group;" ::: "memory"); }
__device__ __forceinline__ void cp_wait0()  { asm volatile("cp.async.wait_group 0;" ::: "memory"); }

// ---------------------------------------------------------------------------
// Kernel 1: fold q[v] = W @ p_half  (4 vectors of 64)
//   v=0: W_edge @ p_node[0:64]   (a_self)
//   v=1: W_node @ p_node[64:128] (a_nb)
//   v=2: W_edge @ p_edge[0:64]   (b_self)
//   v=3: W_edge @ p_edge[64:128] (b_nb)
// ---------------------------------------------------------------------------
__global__ void prep_q_kernel(const float* __restrict__ Wn, const float* __restrict__ We,
                              const float* __restrict__ pn, const float* __restrict__ pe) {
  int t = threadIdx.x;            // 256 threads
  int v = t >> 6, d = t & 63;
  const float* W = (v == 1) ? Wn : We;
  const float* p = (v == 0) ? pn : (v == 1) ? (pn + 64) : (v == 2) ? pe : (pe + 64);
  float s = 0.f;
  #pragma unroll
  for (int e = 0; e < 64; e++) s += W[d * 64 + e] * p[e];
  g_q[t] = s;
}

// ---------------------------------------------------------------------------
// Kernel 2: per-row scalars + their exps (one warp per index i)
// ---------------------------------------------------------------------------
__global__ void prep_scalar_kernel(const float* __restrict__ nf, const float* __restrict__ ef) {
  int warp = threadIdx.x >> 5, lane = threadIdx.x & 31;
  int i = blockIdx.x * 8 + warp;
  float2 e = ((const float2*)(ef + (size_t)i * 64))[lane];
  float2 n = ((const float2*)(nf + (size_t)i * 64))[lane];
  float2 q0 = ((const float2*)(g_q +   0))[lane];
  float2 q1 = ((const float2*)(g_q +  64))[lane];
  float2 q2 = ((const float2*)(g_q + 128))[lane];
  float2 q3 = ((const float2*)(g_q + 192))[lane];
  float p0 = e.x * q0.x + e.y * q0.y;   // a_self (edge feats)
  float p1 = n.x * q1.x + n.y * q1.y;   // a_nb   (node feats)
  float p2 = e.x * q2.x + e.y * q2.y;   // b_self
  float p3 = e.x * q3.x + e.y * q3.y;   // b_nb
  #pragma unroll
  for (int o = 16; o > 0; o >>= 1) {
    p0 += __shfl_xor_sync(0xffffffffu, p0, o);
    p1 += __shfl_xor_sync(0xffffffffu, p1, o);
    p2 += __shfl_xor_sync(0xffffffffu, p2, o);
    p3 += __shfl_xor_sync(0xffffffffu, p3, o);
  }
  if (lane == 0) {
    g_rA[0][i] = p0;  g_rEA[0][i] = expf(p0);  g_rEA2[0][i] = expf(0.01f * p0);
    g_cB[0][i] = p1;  g_cEB[0][i] = expf(p1);  g_cEB2[0][i] = expf(0.01f * p1);
    g_rA[1][i] = p2;  g_rEA[1][i] = expf(p2);  g_rEA2[1][i] = expf(0.01f * p2);
    g_cB[1][i] = p3;  g_cEB[1][i] = expf(p3);  g_cEB2[1][i] = expf(0.01f * p3);
  }
}

// ---------------------------------------------------------------------------
// Chunk loader: adjacency block (TKxTM int32), X block (TKx64 f32), b-triple
// ---------------------------------------------------------------------------
__device__ __forceinline__ void load_chunk(char* sm, int buf, int ch,
    const int* __restrict__ adjG, const float* __restrict__ X,
    const float* __restrict__ cB, const float* __restrict__ cEB,
    const float* __restrict__ cEB2, int i0, int t) {
  char* sAdj = sm + (buf ? OFF_ADJ1 : OFF_ADJ0);
  char* sX   = sm + (buf ? OFF_X1   : OFF_X0);
  char* sBV  = sm + (buf ? OFF_BV1  : OFF_BV0);
  int k0 = ch * TK;
  const char* adjB = (const char*)adjG;
  #pragma unroll
  for (int u = t; u < 2048; u += NTH) {                 // 64 rows x 512 B
    int kk = u >> 5, o = u & 31;
    cp16(sAdj + (size_t)kk * 512 + o * 16,
         adjB + (((size_t)(k0 + kk) * EDIM + i0) << 2) + (size_t)o * 16);
  }
  #pragma unroll
  for (int u = t; u < 1024; u += NTH) {                 // 64 rows x 256 B
    int kk = u >> 4, o = u & 15;
    cp16(sX + (size_t)kk * 256 + o * 16,
         (const char*)X + ((size_t)(k0 + kk) << 8) + (size_t)o * 16);
  }
  if (t < 48) {
    int arr = t >> 4, o = t & 15;
    const float* src = (arr == 0) ? cB : (arr == 1) ? cEB : cEB2;
    cp16(sBV + arr * 256 + o * 16, (const char*)(src + k0) + (size_t)o * 16);
  }
}

// ---------------------------------------------------------------------------
// Main aggregation kernel. grid = (64, 1, 2): z = side (0 nodes, 1 edges).
// Computes per row i: acc[d] = sum_j m_ij * w_ij * X[j][d], Z, cnt, then
// out_row = leaky((acc / (Z*cnt)) @ W)  written to d_out cols [side*64, +64).
// w factorization: w = (a_i+b_j >= 0) ? ea_i*eb_j : ea2_i*eb2_j  (no MUFU in loop)
// mask recovered from P tile as (P > 0) since w is strictly positive.
// ---------------------------------------------------------------------------
__global__ void __launch_bounds__(NTH, 1)
agg_kernel(const float* __restrict__ nf, const float* __restrict__ ef,
           const int* __restrict__ e2e, const int* __restrict__ n2e,
           const float* __restrict__ Wn, const float* __restrict__ We,
           float* __restrict__ out) {
  extern __shared__ char sm[];
  const int side = blockIdx.z;
  const int*   adjG = side ? e2e : n2e;     // mask[i][j] = adj[j*EDIM + i]
  const float* X    = side ? ef  : nf;
  const float* W    = side ? We  : Wn;
  const float* cB   = g_cB [side];
  const float* cEB  = g_cEB[side];
  const float* cEB2 = g_cEB2[side];
  const int i0 = blockIdx.x * TM;
  const int t  = threadIdx.x;

  float* sRows = (float*)(sm + OFF_ROWS);
  float* sP    = (float*)(sm + OFF_P);
  float* sZC   = (float*)(sm + OFF_ZC);

  if (t < TM) {
    sRows[t]          = g_rA  [side][i0 + t];
    sRows[TM + t]     = g_rEA [side][i0 + t];
    sRows[2 * TM + t] = g_rEA2[side][i0 + t];
  }

  load_chunk(sm, 0, 0, adjG, X, cB, cEB, cEB2, i0, t);
  cp_commit();

  float acc[4][8] = {};
  float zr[4] = {0.f, 0.f, 0.f, 0.f};
  float cr[4] = {0.f, 0.f, 0.f, 0.f};
  const int tx = t & 7, ty = t >> 3;
  const int r0 = ty * 4, c0 = tx * 8;
  const int warp = t >> 5, lane4 = (t & 31) * 4;

  cp_wait0();
  __syncthreads();

  // hoist per-thread row quantities for phase 1 (invariant across chunks)
  float4 aR   = *(const float4*)(sRows + lane4);
  float4 eaR  = *(const float4*)(sRows + TM + lane4);
  float4 ea2R = *(const float4*)(sRows + 2 * TM + lane4);

  for (int ch = 0; ch < NCHUNK; ch++) {
    int cur = ch & 1;
    if (ch + 1 < NCHUNK) {
      load_chunk(sm, cur ^ 1, ch + 1, adjG, X, cB, cEB, cEB2, i0, t);
      cp_commit();
    }
    const int*   sAdj = (const int*)  (sm + (cur ? OFF_ADJ1 : OFF_ADJ0));
    const float* sBV  = (const float*)(sm + (cur ? OFF_BV1  : OFF_BV0));

    // phase 1: generate P tile [TK][TM]
    #pragma unroll
    for (int p = 0; p < 8; p++) {
      int kk = (p << 3) | warp;
      int4 m = *(const int4*)(sAdj + kk * TM + lane4);
      float bK = sBV[kk], ebK = sBV[64 + kk], eb2K = sBV[128 + kk];
      float4 w;
      w.x = (m.x > 0) ? ((aR.x + bK >= 0.f) ? eaR.x * ebK : ea2R.x * eb2K) : 0.f;
      w.y = (m.y > 0) ? ((aR.y + bK >= 0.f) ? eaR.y * ebK : ea2R.y * eb2K) : 0.f;
      w.z = (m.z > 0) ? ((aR.z + bK >= 0.f) ? eaR.z * ebK : ea2R.z * eb2K) : 0.f;
      w.w = (m.w > 0) ? ((aR.w + bK >= 0.f) ? eaR.w * ebK : ea2R.w * eb2K) : 0.f;
      *(float4*)(sP + kk * TM + lane4) = w;
    }
    __syncthreads();

    // phase 2: acc += P^T-slice x X-slice (4x8 microtile per thread)
    const float* sX = (const float*)(sm + (cur ? OFF_X1 : OFF_X0));
    #pragma unroll 8
    for (int kk = 0; kk < TK; kk++) {
      float4 p4 = *(const float4*)(sP + kk * TM + r0);
      float4 xa = *(const float4*)(sX + kk * 64 + c0);
      float4 xb = *(const float4*)(sX + kk * 64 + c0 + 4);
      float pr[4] = {p4.x, p4.y, p4.z, p4.w};
      float xv[8] = {xa.x, xa.y, xa.z, xa.w, xb.x, xb.y, xb.z, xb.w};
      #pragma unroll
      for (int rr = 0; rr < 4; rr++)
        #pragma unroll
        for (int cc = 0; cc < 8; cc++)
          acc[rr][cc] = fmaf(pr[rr], xv[cc], acc[rr][cc]);
      if (tx == 0) {
        #pragma unroll
        for (int rr = 0; rr < 4; rr++) {
          zr[rr] += pr[rr];
          cr[rr] += (pr[rr] > 0.f) ? 1.f : 0.f;
        }
      }
    }
    cp_wait0();
    __syncthreads();
  }

  // ---- epilogue: normalize, project through W, leaky, store ----
  if (tx == 0) {
    #pragma unroll
    for (int rr = 0; rr < 4; rr++) {
      sZC[r0 + rr]      = zr[rr];
      sZC[TM + r0 + rr] = cr[rr];
    }
  }
  __syncthreads();

  float* sM = (float*)(sm + OFF_M);   // reuses adjacency region (dead now)
  float* sW = (float*)(sm + OFF_W);
  #pragma unroll
  for (int rr = 0; rr < 4; rr++) {
    float inv = 1.f / (sZC[r0 + rr] * sZC[TM + r0 + rr]);
    #pragma unroll
    for (int cc = 0; cc < 8; cc++)
      sM[(r0 + rr) * MSTRIDE + c0 + cc] = acc[rr][cc] * inv;
  }
  for (int u = t; u < 1024; u += NTH)
    ((float4*)sW)[u] = ((const float4*)W)[u];
  __syncthreads();

  float o[4][8] = {};
  #pragma unroll 8
  for (int k = 0; k < 64; k++) {
    float mr[4];
    #pragma unroll
    for (int rr = 0; rr < 4; rr++) mr[rr] = sM[(r0 + rr) * MSTRIDE + k];
    float4 wa = *(const float4*)(sW + k * 64 + c0);
    float4 wb = *(const float4*)(sW + k * 64 + c0 + 4);
    float wv[8] = {wa.x, wa.y, wa.z, wa.w, wb.x, wb.y, wb.z, wb.w};
    #pragma unroll
    for (int rr = 0; rr < 4; rr++)
      #pragma unroll
      for (int cc = 0; cc < 8; cc++)
        o[rr][cc] = fmaf(mr[rr], wv[cc], o[rr][cc]);
  }

  #pragma unroll
  for (int rr = 0; rr < 4; rr++) {
    float v[8];
    #pragma unroll
    for (int cc = 0; cc < 8; cc++) {
      float x = o[rr][cc];
      v[cc] = (x >= 0.f) ? x : 0.01f * x;
    }
    float* op = out + (size_t)(i0 + r0 + rr) * 128 + side * 64 + c0;
    *(float4*)(op)     = make_float4(v[0], v[1], v[2], v[3]);
    *(float4*)(op + 4) = make_float4(v[4], v[5], v[6], v[7]);
  }
}

// ---------------------------------------------------------------------------
extern "C" void kernel_launch(void* const* d_in, const int* in_sizes, int n_in,
                              void* d_out, int out_size) {
  const float* nf  = (const float*)d_in[0];   // node_features [8192,64]
  const float* ef  = (const float*)d_in[1];   // edge_features [8192,64]
  const int*   e2e = (const int*)  d_in[2];   // [E,E]
  const int*   n2e = (const int*)  d_in[3];   // [N,E]
  const float* Wn  = (const float*)d_in[4];   // [64,64]
  const float* We  = (const float*)d_in[5];   // [64,64]
  const float* pn  = (const float*)d_in[6];   // [128]
  const float* pe  = (const float*)d_in[7];   // [128]
  float* out = (float*)d_out;                 // [8192,128]

  cudaFuncSetAttribute(agg_kernel, cudaFuncAttributeMaxDynamicSharedMemorySize, SMEM_BYTES);

  prep_q_kernel<<<1, 256>>>(Wn, We, pn, pe);
  prep_scalar_kernel<<<EDIM / 8, 256>>>(nf, ef);
  dim3 grid(EDIM / TM, 1, 2);
  agg_kernel<<<grid, NTH, SMEM_BYTES>>>(nf, ef, e2e, n2e, Wn, We, out);
}

// round 4
// speedup vs baseline: 1.0780x; 1.0780x over previous
#include <cuda_runtime.h>
#include <math.h>

#define EDIM 8192      // N == E == 8192
#define TM   128       // rows per CTA
#define TK   64        // K-chunk
#define NTH  256
#define NCHUNK (EDIM / TK)

// ---- shared memory layout (bytes) ----
#define OFF_ADJ0 0          // 32 KB int32 adjacency chunk, buf 0
#define OFF_ADJ1 32768      // buf 1
#define OFF_X0   65536      // 16 KB X chunk, buf 0
#define OFF_X1   81920      // buf 1
#define OFF_BV0  98304      // 768 B: b[64], eb[64], eb2[64]
#define OFF_BV1  99072
#define OFF_P    99840      // 32 KB P tile [TK][TM]
#define OFF_ROWS 132608     // 1.5 KB: a[128], ea[128], ea2[128]
#define OFF_ZC   134144     // 1 KB: z[128], cnt[128]
#define OFF_ZP   135168     // 8 KB: per-warp partials z[8][128], c[8][128]
#define SMEM_BYTES 143360
// epilogue reuse of the front of smem
#define OFF_M    0          // means, stride 65 floats (conflict-free column reads)
#define MSTRIDE  65
#define OFF_W    33280      // 16 KB weight matrix

// ---- device scratch (no mallocs allowed) ----
__device__ __align__(16) float g_rA  [2][EDIM];   // per-row score
__device__ __align__(16) float g_rEA [2][EDIM];   // exp(row)
__device__ __align__(16) float g_rEA2[2][EDIM];   // exp(0.01*row)
__device__ __align__(16) float g_cB  [2][EDIM];   // per-col score
__device__ __align__(16) float g_cEB [2][EDIM];
__device__ __align__(16) float g_cEB2[2][EDIM];

__device__ __forceinline__ void cp16(void* dst, const void* src) {
  unsigned sa = (unsigned)__cvta_generic_to_shared(dst);
  asm volatile("cp.async.cg.shared.global [%0], [%1], 16;" :: "r"(sa), "l"(src) : "memory");
}
__device__ __forceinline__ void cp_commit() { asm volatile("cp.async.commit_group;" ::: "memory"); }
__device__ __forceinline__ void cp_wait0()  { asm volatile("cp.async.wait_group 0;" ::: "memory"); }

// ---- Blackwell packed dual-fp32 FMA (ptxas never emits this from C++) ----
__device__ __forceinline__ void ffma2(unsigned long long& d,
                                      unsigned long long a, unsigned long long b) {
  asm("fma.rn.f32x2 %0, %1, %2, %0;" : "+l"(d) : "l"(a), "l"(b));
}
__device__ __forceinline__ unsigned long long pack2(float v) {
  unsigned long long r;
  asm("mov.b64 %0, {%1, %1};" : "=l"(r) : "f"(v));
  return r;
}
__device__ __forceinline__ void unpack2(unsigned long long v, float& lo, float& hi) {
  asm("mov.b64 {%0, %1}, %2;" : "=f"(lo), "=f"(hi) : "l"(v));
}

// ---------------------------------------------------------------------------
// Fused prep kernel: each block recomputes the four folded q = W@p vectors in
// smem (cheap), then 8 warps each produce the row/col scalar triples for one
// index i. 1024 blocks x 8 rows = 8192.
// ---------------------------------------------------------------------------
__global__ void prep_kernel(const float* __restrict__ nf, const float* __restrict__ ef,
                            const float* __restrict__ Wn, const float* __restrict__ We,
                            const float* __restrict__ pn, const float* __restrict__ pe) {
  __shared__ float sq[256];
  int t = threadIdx.x;
  {
    int v = t >> 6, d = t & 63;
    const float* W = (v == 1) ? Wn : We;
    const float* p = (v == 0) ? pn : (v == 1) ? (pn + 64) : (v == 2) ? pe : (pe + 64);
    float s = 0.f;
    #pragma unroll
    for (int e = 0; e < 64; e++) s += W[d * 64 + e] * p[e];
    sq[t] = s;
  }
  __syncthreads();

  int warp = t >> 5, lane = t & 31;
  int i = blockIdx.x * 8 + warp;
  float2 e = ((const float2*)(ef + (size_t)i * 64))[lane];
  float2 n = ((const float2*)(nf + (size_t)i * 64))[lane];
  float2 q0 = ((const float2*)(sq +   0))[lane];
  float2 q1 = ((const float2*)(sq +  64))[lane];
  float2 q2 = ((const float2*)(sq + 128))[lane];
  float2 q3 = ((const float2*)(sq + 192))[lane];
  float p0 = e.x * q0.x + e.y * q0.y;   // a_self (edge feats)
  float p1 = n.x * q1.x + n.y * q1.y;   // a_nb   (node feats)
  float p2 = e.x * q2.x + e.y * q2.y;   // b_self
  float p3 = e.x * q3.x + e.y * q3.y;   // b_nb
  #pragma unroll
  for (int o = 16; o > 0; o >>= 1) {
    p0 += __shfl_xor_sync(0xffffffffu, p0, o);
    p1 += __shfl_xor_sync(0xffffffffu, p1, o);
    p2 += __shfl_xor_sync(0xffffffffu, p2, o);
    p3 += __shfl_xor_sync(0xffffffffu, p3, o);
  }
  if (lane == 0) {
    g_rA[0][i] = p0;  g_rEA[0][i] = expf(p0);  g_rEA2[0][i] = expf(0.01f * p0);
    g_cB[0][i] = p1;  g_cEB[0][i] = expf(p1);  g_cEB2[0][i] = expf(0.01f * p1);
    g_rA[1][i] = p2;  g_rEA[1][i] = expf(p2);  g_rEA2[1][i] = expf(0.01f * p2);
    g_cB[1][i] = p3;  g_cEB[1][i] = expf(p3);  g_cEB2[1][i] = expf(0.01f * p3);
  }
}

// ---------------------------------------------------------------------------
// Chunk loader: adjacency block (TKxTM int32), X block (TKx64 f32), b-triple
// ---------------------------------------------------------------------------
__device__ __forceinline__ void load_chunk(char* sm, int buf, int ch,
    const int* __restrict__ adjG, const float* __restrict__ X,
    const float* __restrict__ cB, const float* __restrict__ cEB,
    const float* __restrict__ cEB2, int i0, int t) {
  char* sAdj = sm + (buf ? OFF_ADJ1 : OFF_ADJ0);
  char* sX   = sm + (buf ? OFF_X1   : OFF_X0);
  char* sBV  = sm + (buf ? OFF_BV1  : OFF_BV0);
  int k0 = ch * TK;
  const char* adjB = (const char*)adjG;
  #pragma unroll
  for (int u = t; u < 2048; u += NTH) {                 // 64 rows x 512 B
    int kk = u >> 5, o = u & 31;
    cp16(sAdj + (size_t)kk * 512 + o * 16,
         adjB + (((size_t)(k0 + kk) * EDIM + i0) << 2) + (size_t)o * 16);
  }
  #pragma unroll
  for (int u = t; u < 1024; u += NTH) {                 // 64 rows x 256 B
    int kk = u >> 4, o = u & 15;
    cp16(sX + (size_t)kk * 256 + o * 16,
         (const char*)X + ((size_t)(k0 + kk) << 8) + (size_t)o * 16);
  }
  if (t < 48) {
    int arr = t >> 4, o = t & 15;
    const float* src = (arr == 0) ? cB : (arr == 1) ? cEB : cEB2;
    cp16(sBV + arr * 256 + o * 16, (const char*)(src + k0) + (size_t)o * 16);
  }
}

// ---------------------------------------------------------------------------
// Main aggregation kernel. grid = (64, 1, 2): z = side (0 nodes, 1 edges).
// Phase 1 generates the P tile AND accumulates per-warp Z/cnt partials.
// Phase 2 is a pure FFMA2 microtile GEMM: acc += P^T x X.
// w factorization: w = (a_i+b_j >= 0) ? ea_i*eb_j : ea2_i*eb2_j  (no MUFU)
// ---------------------------------------------------------------------------
__global__ void __launch_bounds__(NTH, 1)
agg_kernel(const float* __restrict__ nf, const float* __restrict__ ef,
           const int* __restrict__ e2e, const int* __restrict__ n2e,
           const float* __restrict__ Wn, const float* __restrict__ We,
           float* __restrict__ out) {
  extern __shared__ char sm[];
  const int side = blockIdx.z;
  const int*   adjG = side ? e2e : n2e;     // mask[i][j] = adj[j*EDIM + i]
  const float* X    = side ? ef  : nf;
  const float* W    = side ? We  : Wn;
  const float* cB   = g_cB [side];
  const float* cEB  = g_cEB[side];
  const float* cEB2 = g_cEB2[side];
  const int i0 = blockIdx.x * TM;
  const int t  = threadIdx.x;

  float* sRows = (float*)(sm + OFF_ROWS);
  float* sP    = (float*)(sm + OFF_P);
  float* sZC   = (float*)(sm + OFF_ZC);
  float* sZP   = (float*)(sm + OFF_ZP);     // [8][128] z then [8][128] c

  if (t < TM) {
    sRows[t]          = g_rA  [side][i0 + t];
    sRows[TM + t]     = g_rEA [side][i0 + t];
    sRows[2 * TM + t] = g_rEA2[side][i0 + t];
  }

  load_chunk(sm, 0, 0, adjG, X, cB, cEB, cEB2, i0, t);
  cp_commit();

  unsigned long long acc[4][4];             // 4 rows x 4 f32x2 pairs (8 cols)
  #pragma unroll
  for (int rr = 0; rr < 4; rr++)
    #pragma unroll
    for (int cc = 0; cc < 4; cc++) acc[rr][cc] = 0ull;

  float z4[4] = {0.f, 0.f, 0.f, 0.f};       // per-warp Z partials (phase 1)
  float c4[4] = {0.f, 0.f, 0.f, 0.f};       // per-warp cnt partials

  const int tx = t & 7, ty = t >> 3;
  const int r0 = ty * 4, c0 = tx * 8;
  const int warp = t >> 5, lane4 = (t & 31) * 4;

  cp_wait0();
  __syncthreads();

  // hoist per-thread row quantities for phase 1 (invariant across chunks)
  float4 aR   = *(const float4*)(sRows + lane4);
  float4 eaR  = *(const float4*)(sRows + TM + lane4);
  float4 ea2R = *(const float4*)(sRows + 2 * TM + lane4);

  for (int ch = 0; ch < NCHUNK; ch++) {
    int cur = ch & 1;
    if (ch + 1 < NCHUNK) {
      load_chunk(sm, cur ^ 1, ch + 1, adjG, X, cB, cEB, cEB2, i0, t);
      cp_commit();
    }
    const int*   sAdj = (const int*)  (sm + (cur ? OFF_ADJ1 : OFF_ADJ0));
    const float* sBV  = (const float*)(sm + (cur ? OFF_BV1  : OFF_BV0));

    // phase 1: generate P tile [TK][TM] + Z/cnt partials
    #pragma unroll
    for (int p = 0; p < 8; p++) {
      int kk = (p << 3) | warp;
      int4 m = *(const int4*)(sAdj + kk * TM + lane4);
      float bK = sBV[kk], ebK = sBV[64 + kk], eb2K = sBV[128 + kk];
      float4 w;
      w.x = (m.x > 0) ? ((aR.x + bK >= 0.f) ? eaR.x * ebK : ea2R.x * eb2K) : 0.f;
      w.y = (m.y > 0) ? ((aR.y + bK >= 0.f) ? eaR.y * ebK : ea2R.y * eb2K) : 0.f;
      w.z = (m.z > 0) ? ((aR.z + bK >= 0.f) ? eaR.z * ebK : ea2R.z * eb2K) : 0.f;
      w.w = (m.w > 0) ? ((aR.w + bK >= 0.f) ? eaR.w * ebK : ea2R.w * eb2K) : 0.f;
      *(float4*)(sP + kk * TM + lane4) = w;
      z4[0] += w.x; z4[1] += w.y; z4[2] += w.z; z4[3] += w.w;
      c4[0] += (m.x > 0) ? 1.f : 0.f;
      c4[1] += (m.y > 0) ? 1.f : 0.f;
      c4[2] += (m.z > 0) ? 1.f : 0.f;
      c4[3] += (m.w > 0) ? 1.f : 0.f;
    }
    __syncthreads();

    // phase 2: acc += P^T-slice x X-slice, pure FFMA2 (no Z/cnt here)
    const float* sX = (const float*)(sm + (cur ? OFF_X1 : OFF_X0));
    #pragma unroll 4
    for (int kk = 0; kk < TK; kk++) {
      float4 p4 = *(const float4*)(sP + kk * TM + r0);
      ulonglong2 xlo = *(const ulonglong2*)(sX + kk * 64 + c0);      // cols c0..c0+3
      ulonglong2 xhi = *(const ulonglong2*)(sX + kk * 64 + c0 + 4);  // cols c0+4..c0+7
      unsigned long long pp0 = pack2(p4.x), pp1 = pack2(p4.y);
      unsigned long long pp2 = pack2(p4.z), pp3 = pack2(p4.w);
      ffma2(acc[0][0], pp0, xlo.x); ffma2(acc[0][1], pp0, xlo.y);
      ffma2(acc[0][2], pp0, xhi.x); ffma2(acc[0][3], pp0, xhi.y);
      ffma2(acc[1][0], pp1, xlo.x); ffma2(acc[1][1], pp1, xlo.y);
      ffma2(acc[1][2], pp1, xhi.x); ffma2(acc[1][3], pp1, xhi.y);
      ffma2(acc[2][0], pp2, xlo.x); ffma2(acc[2][1], pp2, xlo.y);
      ffma2(acc[2][2], pp2, xhi.x); ffma2(acc[2][3], pp2, xhi.y);
      ffma2(acc[3][0], pp3, xlo.x); ffma2(acc[3][1], pp3, xlo.y);
      ffma2(acc[3][2], pp3, xhi.x); ffma2(acc[3][3], pp3, xhi.y);
    }
    cp_wait0();
    __syncthreads();
  }

  // ---- Z/cnt cross-warp reduction ----
  #pragma unroll
  for (int rr = 0; rr < 4; rr++) {
    sZP[warp * TM + lane4 + rr]            = z4[rr];
    sZP[8 * TM + warp * TM + lane4 + rr]   = c4[rr];
  }
  __syncthreads();
  if (t < TM) {
    float zs = 0.f, cs = 0.f;
    #pragma unroll
    for (int w = 0; w < 8; w++) {
      zs += sZP[w * TM + t];
      cs += sZP[8 * TM + w * TM + t];
    }
    sZC[t]      = zs;
    sZC[TM + t] = cs;
  }
  __syncthreads();

  // ---- epilogue: normalize, project through W, leaky, store ----
  float* sM = (float*)(sm + OFF_M);   // reuses adjacency region (dead now)
  float* sW = (float*)(sm + OFF_W);
  #pragma unroll
  for (int rr = 0; rr < 4; rr++) {
    float inv = 1.f / (sZC[r0 + rr] * sZC[TM + r0 + rr]);
    #pragma unroll
    for (int cc = 0; cc < 4; cc++) {
      float lo, hi;
      unpack2(acc[rr][cc], lo, hi);
      sM[(r0 + rr) * MSTRIDE + c0 + 2 * cc]     = lo * inv;
      sM[(r0 + rr) * MSTRIDE + c0 + 2 * cc + 1] = hi * inv;
    }
  }
  for (int u = t; u < 1024; u += NTH)
    ((float4*)sW)[u] = ((const float4*)W)[u];
  __syncthreads();

  float o[4][8] = {};
  #pragma unroll 8
  for (int k = 0; k < 64; k++) {
    float mr[4];
    #pragma unroll
    for (int rr = 0; rr < 4; rr++) mr[rr] = sM[(r0 + rr) * MSTRIDE + k];
    float4 wa = *(const float4*)(sW + k * 64 + c0);
    float4 wb = *(const float4*)(sW + k * 64 + c0 + 4);
    float wv[8] = {wa.x, wa.y, wa.z, wa.w, wb.x, wb.y, wb.z, wb.w};
    #pragma unroll
    for (int rr = 0; rr < 4; rr++)
      #pragma unroll
      for (int cc = 0; cc < 8; cc++)
        o[rr][cc] = fmaf(mr[rr], wv[cc], o[rr][cc]);
  }

  #pragma unroll
  for (int rr = 0; rr < 4; rr++) {
    float v[8];
    #pragma unroll
    for (int cc = 0; cc < 8; cc++) {
      float x = o[rr][cc];
      v[cc] = (x >= 0.f) ? x : 0.01f * x;
    }
    float* op = out + (size_t)(i0 + r0 + rr) * 128 + side * 64 + c0;
    *(float4*)(op)     = make_float4(v[0], v[1], v[2], v[3]);
    *(float4*)(op + 4) = make_float4(v[4], v[5], v[6], v[7]);
  }
}

// ---------------------------------------------------------------------------
extern "C" void kernel_launch(void* const* d_in, const int* in_sizes, int n_in,
                              void* d_out, int out_size) {
  const float* nf  = (const float*)d_in[0];   // node_features [8192,64]
  const float* ef  = (const float*)d_in[1];   // edge_features [8192,64]
  const int*   e2e = (const int*)  d_in[2];   // [E,E]
  const int*   n2e = (const int*)  d_in[3];   // [N,E]
  const float* Wn  = (const float*)d_in[4];   // [64,64]
  const float* We  = (const float*)d_in[5];   // [64,64]
  const float* pn  = (const float*)d_in[6];   // [128]
  const float* pe  = (const float*)d_in[7];   // [128]
  float* out = (float*)d_out;                 // [8192,128]

  cudaFuncSetAttribute(agg_kernel, cudaFuncAttributeMaxDynamicSharedMemorySize, SMEM_BYTES);

  prep_kernel<<<EDIM / 8, 256>>>(nf, ef, Wn, We, pn, pe);
  dim3 grid(EDIM / TM, 1, 2);
  agg_kernel<<<grid, NTH, SMEM_BYTES>>>(nf, ef, e2e, n2e, Wn, We, out);
}

// round 6
// speedup vs baseline: 2.8959x; 2.6864x over previous
#include <cuda_runtime.h>
#include <cuda_bf16.h>
#include <math.h>

#define EDIM 8192      // N == E == 8192
#define TM   128       // rows per CTA
#define TK   64        // K-chunk
#define NTH  256
#define NCHUNK (EDIM / TK)

// ---- shared memory layout (bytes) ----
#define OFF_ADJ0 0          // 32 KB adjacency chunk [64 k][128 i] int32
#define OFF_ADJ1 32768
#define OFF_PH   65536      // 16 KB Ph tile [128 i][64 k] bf16, swizzled rows
#define OFF_PL   81920
#define OFF_X    98304      // 2 bufs x 16 KB (Xh 8KB + Xl 8KB) [64 d][64 k] bf16
#define OFF_BV0  131072     // 1 KB packed col triples float4[64]
#define OFF_BV1  132096
#define OFF_ROWS 133120     // 1.5 KB a/ea/ea2[128]
#define OFF_ZP   134656     // 2 KB partials z[2][128], c[2][128]
#define OFF_ZC   136704     // 1 KB z[128], cnt[128]
#define SMEM_BYTES 137728
// epilogue reuse of dead adjacency region
#define OFF_M    0
#define MSTRIDE  65
#define OFF_W    34816

// ---- device scratch ----
__device__ __align__(16) float g_rA  [2][EDIM];
__device__ __align__(16) float g_rEA [2][EDIM];
__device__ __align__(16) float g_rEA2[2][EDIM];
__device__ __align__(16) float4 g_cPack[2 * EDIM];          // {b, eb, eb2, 0}
__device__ __align__(16) __nv_bfloat16 g_XhT[2][64 * EDIM]; // X^T hi split [d][k]
__device__ __align__(16) __nv_bfloat16 g_XlT[2][64 * EDIM]; // X^T lo split

// ---- PTX helpers ----
__device__ __forceinline__ unsigned smem_u32(const void* p) {
  unsigned a;
  asm("{ .reg .u64 t; cvta.to.shared.u64 t, %1; cvt.u32.u64 %0, t; }" : "=r"(a) : "l"(p));
  return a;
}
__device__ __forceinline__ void cp16(void* dst, const void* src) {
  unsigned sa = smem_u32(dst);
  asm volatile("cp.async.cg.shared.global [%0], [%1], 16;" :: "r"(sa), "l"(src) : "memory");
}
__device__ __forceinline__ void cp_commit() { asm volatile("cp.async.commit_group;" ::: "memory"); }
__device__ __forceinline__ void cp_wait0()  { asm volatile("cp.async.wait_group 0;" ::: "memory"); }

__device__ __forceinline__ void ldsm4(unsigned& r0, unsigned& r1, unsigned& r2, unsigned& r3,
                                      unsigned addr) {
  asm volatile("ldmatrix.sync.aligned.m8n8.x4.shared.b16 {%0,%1,%2,%3}, [%4];"
               : "=r"(r0), "=r"(r1), "=r"(r2), "=r"(r3) : "r"(addr));
}
__device__ __forceinline__ void mma16816(float* c, const unsigned* a, unsigned b0, unsigned b1) {
  asm volatile("mma.sync.aligned.m16n8k16.row.col.f32.bf16.bf16.f32 "
               "{%0,%1,%2,%3}, {%4,%5,%6,%7}, {%8,%9}, {%0,%1,%2,%3};"
               : "+f"(c[0]), "+f"(c[1]), "+f"(c[2]), "+f"(c[3])
               : "r"(a[0]), "r"(a[1]), "r"(a[2]), "r"(a[3]), "r"(b0), "r"(b1));
}

// ---------------------------------------------------------------------------
// Prep: q = W@p folds, per-index score scalars + exps, packed col triples,
// and bf16-split TRANSPOSED feature matrices XhT/XlT (K-major B operands).
// ---------------------------------------------------------------------------
__global__ void prep_kernel(const float* __restrict__ nf, const float* __restrict__ ef,
                            const float* __restrict__ Wn, const float* __restrict__ We,
                            const float* __restrict__ pn, const float* __restrict__ pe) {
  __shared__ float sq[256];
  __shared__ float tN[64 * 65];
  __shared__ float tE[64 * 65];
  int t = threadIdx.x;
  int i0 = blockIdx.x * 64;
  {
    int v = t >> 6, d = t & 63;
    const float* W = (v == 1) ? Wn : We;
    const float* p = (v == 0) ? pn : (v == 1) ? (pn + 64) : (v == 2) ? pe : (pe + 64);
    float s = 0.f;
    #pragma unroll
    for (int e = 0; e < 64; e++) s += W[d * 64 + e] * p[e];
    sq[t] = s;
  }
  for (int u = t; u < 1024; u += 256) {
    int r = u >> 4, c = (u & 15) * 4;
    float4 v4 = *(const float4*)(nf + (size_t)(i0 + r) * 64 + c);
    tN[r*65+c] = v4.x; tN[r*65+c+1] = v4.y; tN[r*65+c+2] = v4.z; tN[r*65+c+3] = v4.w;
    float4 e4 = *(const float4*)(ef + (size_t)(i0 + r) * 64 + c);
    tE[r*65+c] = e4.x; tE[r*65+c+1] = e4.y; tE[r*65+c+2] = e4.z; tE[r*65+c+3] = e4.w;
  }
  __syncthreads();
  {
    int v = t & 3, r = t >> 2;
    const float* tl = (v == 1) ? tN : tE;
    const float* q = sq + v * 64;
    float s = 0.f;
    #pragma unroll
    for (int e = 0; e < 64; e++) s += tl[r * 65 + e] * q[e];
    int i = i0 + r;
    float es = expf(s), es2 = expf(0.01f * s);
    if (v == 0)      { g_rA[0][i] = s; g_rEA[0][i] = es; g_rEA2[0][i] = es2; }
    else if (v == 2) { g_rA[1][i] = s; g_rEA[1][i] = es; g_rEA2[1][i] = es2; }
    else if (v == 1) { g_cPack[i]        = make_float4(s, es, es2, 0.f); }
    else             { g_cPack[EDIM + i] = make_float4(s, es, es2, 0.f); }
  }
  for (int u = t; u < 4096; u += 256) {
    int d = u >> 6, ii = u & 63;
    size_t o = (size_t)d * EDIM + i0 + ii;
    float x = tN[ii * 65 + d];
    __nv_bfloat16 h = __float2bfloat16_rn(x);
    g_XhT[0][o] = h;
    g_XlT[0][o] = __float2bfloat16_rn(x - __bfloat162float(h));
    float y = tE[ii * 65 + d];
    __nv_bfloat16 g = __float2bfloat16_rn(y);
    g_XhT[1][o] = g;
    g_XlT[1][o] = __float2bfloat16_rn(y - __bfloat162float(g));
  }
}

// ---- chunk loaders ----
__device__ __forceinline__ void load_adj_bv(char* sm, int pb, int ch,
    const int* __restrict__ adjG, const float4* __restrict__ cPak, int i0, int t) {
  char* sAdj = sm + (pb ? OFF_ADJ1 : OFF_ADJ0);
  char* sBV  = sm + (pb ? OFF_BV1  : OFF_BV0);
  int k0 = ch * TK;
  const char* adjB = (const char*)adjG;
  #pragma unroll
  for (int u = t; u < 2048; u += NTH) {
    int kk = u >> 5, o = u & 31;
    cp16(sAdj + (size_t)kk * 512 + o * 16,
         adjB + (((size_t)(k0 + kk) * EDIM + i0) << 2) + (size_t)o * 16);
  }
  if (t < 64) cp16(sBV + t * 16, (const char*)(cPak + k0 + t));
}
__device__ __forceinline__ void load_X(char* sm, int xb, int ch,
    const __nv_bfloat16* __restrict__ XhT, const __nv_bfloat16* __restrict__ XlT, int t) {
  char* sXh = sm + OFF_X + xb * 16384;
  char* sXl = sXh + 8192;
  int k0 = ch * TK;
  #pragma unroll
  for (int u = t; u < 512; u += NTH) {
    int d = u >> 3, o = (u & 7) * 16;
    unsigned off = d * 128 + o;
    unsigned sw = off ^ ((off >> 3) & 0x70);   // = off ^ ((d&7)*16)
    cp16(sXh + sw, (const char*)(XhT + (size_t)d * EDIM + k0) + o);
  }
  #pragma unroll
  for (int u = t; u < 512; u += NTH) {
    int d = u >> 3, o = (u & 7) * 16;
    unsigned off = d * 128 + o;
    unsigned sw = off ^ ((off >> 3) & 0x70);
    cp16(sXl + sw, (const char*)(XlT + (size_t)d * EDIM + k0) + o);
  }
}

// ---------------------------------------------------------------------------
// Main: phase 1 builds bf16-split P tiles + Z/cnt; phase 2 does
// D += Ph@Xh^T + Ph@Xl^T + Pl@Xh^T via mma.sync.m16n8k16 (tensor pipe).
// Epilogue: normalize by Z*cnt, project through W, leaky, store.
// ---------------------------------------------------------------------------
__global__ void __launch_bounds__(NTH, 1)
agg_kernel(const int* __restrict__ e2e, const int* __restrict__ n2e,
           const float* __restrict__ Wn, const float* __restrict__ We,
           float* __restrict__ out) {
  extern __shared__ char sm[];
  const int side = blockIdx.z;
  const int*   adjG = side ? e2e : n2e;
  const float* W    = side ? We  : Wn;
  const __nv_bfloat16* XhT = g_XhT[side];
  const __nv_bfloat16* XlT = g_XlT[side];
  const float4* cPak = g_cPack + side * EDIM;
  const int i0 = blockIdx.x * TM;
  const int t  = threadIdx.x;
  const int wid = t >> 5, lane = t & 31;
  const unsigned smb = smem_u32(sm);

  float* sRows = (float*)(sm + OFF_ROWS);
  float* sZP   = (float*)(sm + OFF_ZP);
  float* sZC   = (float*)(sm + OFF_ZC);

  if (t < TM) {
    sRows[t]        = g_rA  [side][i0 + t];
    sRows[TM + t]   = g_rEA [side][i0 + t];
    sRows[2*TM + t] = g_rEA2[side][i0 + t];
  }
  load_adj_bv(sm, 0, 0, adjG, cPak, i0, t);
  load_X(sm, 0, 0, XhT, XlT, t);
  cp_commit();
  cp_wait0();
  __syncthreads();

  // ---- phase-1 per-thread constants ----
  const int i = t & 127, khalf = t >> 7;
  const float a_i   = sRows[i];
  const float ea_i  = sRows[TM + i];
  const float ea2_i = sRows[2*TM + i];
  const int sx = (i & 7) << 4;
  const int cb = khalf * 64;              // byte column base in P row
  float zacc = 0.f, cacc = 0.f;

  // ---- phase-2 per-lane address constants ----
  const int m0 = wid * 16;
  const int ar = m0 + (lane & 15);
  const unsigned aRowOff = (unsigned)ar * 128;
  const unsigned aXor = (ar & 7) << 4;
  const unsigned aCol = (lane >> 4) << 4;          // 0 or 16
  const unsigned pPh = smb + OFF_PH, pPl = smb + OFF_PL;
  unsigned dBase[4], dXor[4];
  {
    int dRow = ((lane >> 4) << 3) + (lane & 7);    // 0..15 within np group
    #pragma unroll
    for (int np = 0; np < 4; np++) {
      int d = np * 16 + dRow;
      dBase[np] = (unsigned)d * 128;
      dXor[np]  = (d & 7) << 4;
    }
  }
  const unsigned bCol = ((lane >> 3) & 1) << 4;    // k-block select

  float acc[8][4];
  #pragma unroll
  for (int n = 0; n < 8; n++)
    #pragma unroll
    for (int q = 0; q < 4; q++) acc[n][q] = 0.f;

  for (int ch = 0; ch < NCHUNK; ch++) {
    const int cur = ch & 1;
    if (ch + 1 < NCHUNK) {
      load_adj_bv(sm, cur ^ 1, ch + 1, adjG, cPak, i0, t);
      load_X(sm, cur ^ 1, ch + 1, XhT, XlT, t);
      cp_commit();
    }

    // ---- phase 1: w -> bf16 split tiles + Z/cnt ----
    const int*    sAdj = (const int*)   (sm + (cur ? OFF_ADJ1 : OFF_ADJ0));
    const float4* sBV  = (const float4*)(sm + (cur ? OFF_BV1  : OFF_BV0));
    char* phB = sm + OFF_PH + i * 128;
    char* plB = sm + OFF_PL + i * 128;
    #pragma unroll
    for (int g = 0; g < 4; g++) {
      unsigned ph4[4], pl4[4];
      #pragma unroll
      for (int jj = 0; jj < 4; jj++) {
        int k = khalf * 32 + g * 8 + jj * 2;
        int m0m = sAdj[k * TM + i];
        int m1m = sAdj[(k + 1) * TM + i];
        float4 b0 = sBV[k], b1 = sBV[k + 1];
        float w0 = (a_i + b0.x >= 0.f) ? ea_i * b0.y : ea2_i * b0.z;
        w0 = (m0m > 0) ? w0 : 0.f;
        float w1 = (a_i + b1.x >= 0.f) ? ea_i * b1.y : ea2_i * b1.z;
        w1 = (m1m > 0) ? w1 : 0.f;
        zacc += w0; zacc += w1;
        cacc += (m0m > 0) ? 1.f : 0.f;
        cacc += (m1m > 0) ? 1.f : 0.f;
        unsigned ph;
        asm("cvt.rn.bf16x2.f32 %0, %1, %2;" : "=r"(ph) : "f"(w1), "f"(w0));
        float h0 = __uint_as_float(ph << 16);
        float h1 = __uint_as_float(ph & 0xffff0000u);
        unsigned pl;
        asm("cvt.rn.bf16x2.f32 %0, %1, %2;" : "=r"(pl) : "f"(w1 - h1), "f"(w0 - h0));
        ph4[jj] = ph; pl4[jj] = pl;
      }
      int off = (cb + g * 16) ^ sx;
      *(uint4*)(phB + off) = make_uint4(ph4[0], ph4[1], ph4[2], ph4[3]);
      *(uint4*)(plB + off) = make_uint4(pl4[0], pl4[1], pl4[2], pl4[3]);
    }
    __syncthreads();

    // ---- phase 2: tensor-pipe GEMM on this chunk ----
    const unsigned pXh = smb + OFF_X + cur * 16384;
    const unsigned pXl = pXh + 8192;
    #pragma unroll
    for (int ks = 0; ks < 4; ks++) {
      unsigned ah[4], al[4];
      unsigned aOff = ((unsigned)(ks * 32) + aCol) ^ aXor;
      ldsm4(ah[0], ah[1], ah[2], ah[3], pPh + aRowOff + aOff);
      ldsm4(al[0], al[1], al[2], al[3], pPl + aRowOff + aOff);
      #pragma unroll
      for (int np = 0; np < 4; np++) {
        unsigned bh[4], bl[4];
        unsigned bOff = ((unsigned)(ks * 32) + bCol) ^ dXor[np];
        ldsm4(bh[0], bh[1], bh[2], bh[3], pXh + dBase[np] + bOff);
        ldsm4(bl[0], bl[1], bl[2], bl[3], pXl + dBase[np] + bOff);
        mma16816(acc[2*np],   ah, bh[0], bh[1]);
        mma16816(acc[2*np+1], ah, bh[2], bh[3]);
        mma16816(acc[2*np],   ah, bl[0], bl[1]);
        mma16816(acc[2*np+1], ah, bl[2], bl[3]);
        mma16816(acc[2*np],   al, bh[0], bh[1]);
        mma16816(acc[2*np+1], al, bh[2], bh[3]);
      }
    }
    if (ch + 1 < NCHUNK) cp_wait0();
    __syncthreads();
  }

  // ---- Z/cnt reduction ----
  sZP[khalf * 128 + i]       = zacc;
  sZP[256 + khalf * 128 + i] = cacc;
  __syncthreads();
  if (t < 128) {
    sZC[t]       = sZP[t] + sZP[128 + t];
    sZC[128 + t] = sZP[256 + t] + sZP[384 + t];
  }
  __syncthreads();

  // ---- epilogue: scatter scaled accumulators to sM, load W ----
  float* sM = (float*)(sm + OFF_M);   // dead adjacency region
  float* sW = (float*)(sm + OFF_W);
  {
    int g = lane >> 2, tid4 = lane & 3;
    int r0e = m0 + g, r1e = m0 + g + 8;
    float inv0 = 1.f / (sZC[r0e] * sZC[128 + r0e]);
    float inv1 = 1.f / (sZC[r1e] * sZC[128 + r1e]);
    #pragma unroll
    for (int nb = 0; nb < 8; nb++) {
      int c = nb * 8 + tid4 * 2;
      sM[r0e * MSTRIDE + c]     = acc[nb][0] * inv0;
      sM[r0e * MSTRIDE + c + 1] = acc[nb][1] * inv0;
      sM[r1e * MSTRIDE + c]     = acc[nb][2] * inv1;
      sM[r1e * MSTRIDE + c + 1] = acc[nb][3] * inv1;
    }
  }
  for (int u = t; u < 1024; u += NTH)
    ((float4*)sW)[u] = ((const float4*)W)[u];
  __syncthreads();

  // ---- projection through W + leaky + store ----
  const int tx = t & 7, ty = t >> 3;
  const int r0 = ty * 4, c0 = tx * 8;
  float o[4][8] = {};
  #pragma unroll 8
  for (int k = 0; k < 64; k++) {
    float mr[4];
    #pragma unroll
    for (int rr = 0; rr < 4; rr++) mr[rr] = sM[(r0 + rr) * MSTRIDE + k];
    float4 wa = *(const float4*)(sW + k * 64 + c0);
    float4 wb = *(const float4*)(sW + k * 64 + c0 + 4);
    float wv[8] = {wa.x, wa.y, wa.z, wa.w, wb.x, wb.y, wb.z, wb.w};
    #pragma unroll
    for (int rr = 0; rr < 4; rr++)
      #pragma unroll
      for (int cc = 0; cc < 8; cc++)
        o[rr][cc] = fmaf(mr[rr], wv[cc], o[rr][cc]);
  }
  #pragma unroll
  for (int rr = 0; rr < 4; rr++) {
    float v[8];
    #pragma unroll
    for (int cc = 0; cc < 8; cc++) {
      float x = o[rr][cc];
      v[cc] = (x >= 0.f) ? x : 0.01f * x;
    }
    float* op = out + (size_t)(i0 + r0 + rr) * 128 + side * 64 + c0;
    *(float4*)(op)     = make_float4(v[0], v[1], v[2], v[3]);
    *(float4*)(op + 4) = make_float4(v[4], v[5], v[6], v[7]);
  }
}

// ---------------------------------------------------------------------------
extern "C" void kernel_launch(void* const* d_in, const int* in_sizes, int n_in,
                              void* d_out, int out_size) {
  const float* nf  = (const float*)d_in[0];
  const float* ef  = (const float*)d_in[1];
  const int*   e2e = (const int*)  d_in[2];
  const int*   n2e = (const int*)  d_in[3];
  const float* Wn  = (const float*)d_in[4];
  const float* We  = (const float*)d_in[5];
  const float* pn  = (const float*)d_in[6];
  const float* pe  = (const float*)d_in[7];
  float* out = (float*)d_out;

  cudaFuncSetAttribute(agg_kernel, cudaFuncAttributeMaxDynamicSharedMemorySize, SMEM_BYTES);

  prep_kernel<<<EDIM / 64, 256>>>(nf, ef, Wn, We, pn, pe);
  dim3 grid(EDIM / TM, 1, 2);
  agg_kernel<<<grid, NTH, SMEM_BYTES>>>(e2e, n2e, Wn, We, out);
}

// round 8
// speedup vs baseline: 3.9124x; 1.3510x over previous
#include <cuda_runtime.h>
#include <cuda_bf16.h>
#include <math.h>

#define EDIM 8192      // N == E == 8192
#define TM   128       // rows per CTA
#define TK   64        // K-chunk
#define NTH  256
#define NCHUNK (EDIM / TK)

// ---- shared memory layout (bytes) ----
#define OFF_A    0          // 2 x 32 KB adjacency staging [64 k][128 i] int32
#define OFF_P    65536      // 2 x (Ph 16KB + Pl 16KB) = 64 KB
#define OFF_X    131072     // 4 x 16 KB (Xh 8KB + Xl 8KB) [64 d][64 k] bf16
#define OFF_BV   196608     // 2 x 1 KB packed col triples float4[64]
#define OFF_ZC   198656     // 1 KB z[128], cnt[128]
#define OFF_W    199680     // 16 KB weight matrix (persistent)
#define SMEM_BYTES 216064
// epilogue reuse of dead A+P region
#define OFF_M    0
#define MSTRIDE  65

// named barrier ids
#define BFULL0 1
#define BFULL1 2
#define BFREE0 3
#define BFREE1 4
#define BPROD  5

// ---- device scratch ----
__device__ __align__(16) float g_rA  [2][EDIM];
__device__ __align__(16) float g_rEA [2][EDIM];
__device__ __align__(16) float g_rEA2[2][EDIM];
__device__ __align__(16) float4 g_cPack[2 * EDIM];          // {b, eb, eb2, 0}
__device__ __align__(16) __nv_bfloat16 g_XhT[2][64 * EDIM]; // X^T hi split [d][k]
__device__ __align__(16) __nv_bfloat16 g_XlT[2][64 * EDIM]; // X^T lo split

// ---- PTX helpers ----
__device__ __forceinline__ unsigned smem_u32(const void* p) {
  unsigned a;
  asm("{ .reg .u64 t; cvta.to.shared.u64 t, %1; cvt.u32.u64 %0, t; }" : "=r"(a) : "l"(p));
  return a;
}
__device__ __forceinline__ void cp16(void* dst, const void* src) {
  unsigned sa = smem_u32(dst);
  asm volatile("cp.async.cg.shared.global [%0], [%1], 16;" :: "r"(sa), "l"(src) : "memory");
}
__device__ __forceinline__ void cp_commit() { asm volatile("cp.async.commit_group;" ::: "memory"); }
__device__ __forceinline__ void cp_wait1()  { asm volatile("cp.async.wait_group 1;" ::: "memory"); }

__device__ __forceinline__ void bar_sync(int id, int cnt) {
  asm volatile("bar.sync %0, %1;" :: "r"(id), "r"(cnt) : "memory");
}
__device__ __forceinline__ void bar_arrive(int id, int cnt) {
  asm volatile("bar.arrive %0, %1;" :: "r"(id), "r"(cnt) : "memory");
}

__device__ __forceinline__ void ldsm4(unsigned& r0, unsigned& r1, unsigned& r2, unsigned& r3,
                                      unsigned addr) {
  asm volatile("ldmatrix.sync.aligned.m8n8.x4.shared.b16 {%0,%1,%2,%3}, [%4];"
               : "=r"(r0), "=r"(r1), "=r"(r2), "=r"(r3) : "r"(addr));
}
__device__ __forceinline__ void mma16816(float* c, const unsigned* a, unsigned b0, unsigned b1) {
  asm volatile("mma.sync.aligned.m16n8k16.row.col.f32.bf16.bf16.f32 "
               "{%0,%1,%2,%3}, {%4,%5,%6,%7}, {%8,%9}, {%0,%1,%2,%3};"
               : "+f"(c[0]), "+f"(c[1]), "+f"(c[2]), "+f"(c[3])
               : "r"(a[0]), "r"(a[1]), "r"(a[2]), "r"(a[3]), "r"(b0), "r"(b1));
}

// ---------------------------------------------------------------------------
// Prep: q = W@p folds, per-index score scalars + exps, packed col triples,
// and bf16-split TRANSPOSED feature matrices XhT/XlT.
// ---------------------------------------------------------------------------
__global__ void prep_kernel(const float* __restrict__ nf, const float* __restrict__ ef,
                            const float* __restrict__ Wn, const float* __restrict__ We,
                            const float* __restrict__ pn, const float* __restrict__ pe) {
  __shared__ float sq[256];
  __shared__ float tN[64 * 65];
  __shared__ float tE[64 * 65];
  int t = threadIdx.x;
  int i0 = blockIdx.x * 64;
  {
    int v = t >> 6, d = t & 63;
    const float* W = (v == 1) ? Wn : We;
    const float* p = (v == 0) ? pn : (v == 1) ? (pn + 64) : (v == 2) ? pe : (pe + 64);
    float s = 0.f;
    #pragma unroll
    for (int e = 0; e < 64; e++) s += W[d * 64 + e] * p[e];
    sq[t] = s;
  }
  for (int u = t; u < 1024; u += 256) {
    int r = u >> 4, c = (u & 15) * 4;
    float4 v4 = *(const float4*)(nf + (size_t)(i0 + r) * 64 + c);
    tN[r*65+c] = v4.x; tN[r*65+c+1] = v4.y; tN[r*65+c+2] = v4.z; tN[r*65+c+3] = v4.w;
    float4 e4 = *(const float4*)(ef + (size_t)(i0 + r) * 64 + c);
    tE[r*65+c] = e4.x; tE[r*65+c+1] = e4.y; tE[r*65+c+2] = e4.z; tE[r*65+c+3] = e4.w;
  }
  __syncthreads();
  {
    int v = t & 3, r = t >> 2;
    const float* tl = (v == 1) ? tN : tE;
    const float* q = sq + v * 64;
    float s = 0.f;
    #pragma unroll
    for (int e = 0; e < 64; e++) s += tl[r * 65 + e] * q[e];
    int i = i0 + r;
    float es = expf(s), es2 = expf(0.01f * s);
    if (v == 0)      { g_rA[0][i] = s; g_rEA[0][i] = es; g_rEA2[0][i] = es2; }
    else if (v == 2) { g_rA[1][i] = s; g_rEA[1][i] = es; g_rEA2[1][i] = es2; }
    else if (v == 1) { g_cPack[i]        = make_float4(s, es, es2, 0.f); }
    else             { g_cPack[EDIM + i] = make_float4(s, es, es2, 0.f); }
  }
  for (int u = t; u < 4096; u += 256) {
    int d = u >> 6, ii = u & 63;
    size_t o = (size_t)d * EDIM + i0 + ii;
    float x = tN[ii * 65 + d];
    __nv_bfloat16 h = __float2bfloat16_rn(x);
    g_XhT[0][o] = h;
    g_XlT[0][o] = __float2bfloat16_rn(x - __bfloat162float(h));
    float y = tE[ii * 65 + d];
    __nv_bfloat16 g = __float2bfloat16_rn(y);
    g_XhT[1][o] = g;
    g_XlT[1][o] = __float2bfloat16_rn(y - __bfloat162float(g));
  }
}

// ---- producer chunk loader (128 threads) ----
__device__ __forceinline__ void p_load(char* sm, int b, int ch,
    const int* __restrict__ adjG, const float4* __restrict__ cPak,
    const __nv_bfloat16* __restrict__ XhT, const __nv_bfloat16* __restrict__ XlT,
    int i0, int tp) {
  char* sA = sm + OFF_A + b * 32768;
  int k0 = ch * TK;
  const char* adjB = (const char*)adjG;
  #pragma unroll
  for (int u = tp; u < 2048; u += 128) {
    int kk = u >> 5, o = u & 31;
    cp16(sA + (size_t)kk * 512 + o * 16,
         adjB + (((size_t)(k0 + kk) * EDIM + i0) << 2) + (size_t)o * 16);
  }
  char* sXh = sm + OFF_X + (ch & 3) * 16384;
  char* sXl = sXh + 8192;
  #pragma unroll
  for (int u = tp; u < 512; u += 128) {
    int d = u >> 3, o = (u & 7) * 16;
    unsigned off = d * 128 + o;
    unsigned sw = off ^ ((off >> 3) & 0x70);
    cp16(sXh + sw, (const char*)(XhT + (size_t)d * EDIM + k0) + o);
    cp16(sXl + sw, (const char*)(XlT + (size_t)d * EDIM + k0) + o);
  }
  if (tp < 64) cp16(sm + OFF_BV + b * 1024 + tp * 16, (const char*)(cPak + k0 + tp));
}

// ---------------------------------------------------------------------------
// Main: warp-specialized. Warps 4-7 (producers) build bf16-split P tiles +
// Z/cnt and drive cp.async; warps 0-3 (consumers) run
// D += Ph@Xh^T + Ph@Xl^T + Pl@Xh^T via mma.sync (M=32 rows per warp).
// Named-barrier FULL/FREE handshake per P buffer; no __syncthreads in loop.
// ---------------------------------------------------------------------------
__global__ void __launch_bounds__(NTH, 1)
agg_kernel(const int* __restrict__ e2e, const int* __restrict__ n2e,
           const float* __restrict__ Wn, const float* __restrict__ We,
           float* __restrict__ out) {
  extern __shared__ char sm[];
  const int side = blockIdx.z;
  const int*   adjG = side ? e2e : n2e;
  const float* W    = side ? We  : Wn;
  const __nv_bfloat16* XhT = g_XhT[side];
  const __nv_bfloat16* XlT = g_XlT[side];
  const float4* cPak = g_cPack + side * EDIM;
  const int i0 = blockIdx.x * TM;
  const int t  = threadIdx.x;
  const int wid = t >> 5, lane = t & 31;
  const unsigned smb = smem_u32(sm);

  float* sZC = (float*)(sm + OFF_ZC);
  float* sW  = (float*)(sm + OFF_W);

  float acc[2][8][4];
  #pragma unroll
  for (int mt = 0; mt < 2; mt++)
    #pragma unroll
    for (int nb = 0; nb < 8; nb++)
      #pragma unroll
      for (int q = 0; q < 4; q++) acc[mt][nb][q] = 0.f;

  if (t >= 128) {
    // ================= PRODUCERS (warps 4-7) =================
    const int tp = t - 128;
    const int i  = tp;
    const float a_i   = g_rA  [side][i0 + i];
    const float ea_i  = g_rEA [side][i0 + i];
    const float ea2_i = g_rEA2[side][i0 + i];
    const int sx = (i & 7) << 4;
    float zacc = 0.f, cacc = 0.f;

    p_load(sm, 0, 0, adjG, cPak, XhT, XlT, i0, tp); cp_commit();
    p_load(sm, 1, 1, adjG, cPak, XhT, XlT, i0, tp); cp_commit();

    for (int ch = 0; ch < NCHUNK; ch++) {
      const int b = ch & 1;
      cp_wait1();                       // group for chunk ch complete
      bar_sync(BPROD, 128);             // all producer slices visible
      if (ch >= 2) bar_sync(b ? BFREE1 : BFREE0, 256);   // P[b] free

      const int*    sAdj = (const int*)   (sm + OFF_A  + b * 32768);
      const float4* sBV  = (const float4*)(sm + OFF_BV + b * 1024);
      char* phB = sm + OFF_P + b * 32768 + i * 128;
      char* plB = phB + 16384;
      #pragma unroll
      for (int g = 0; g < 8; g++) {
        unsigned ph4[4], pl4[4];
        #pragma unroll
        for (int jj = 0; jj < 4; jj++) {
          int k = g * 8 + jj * 2;
          int m0m = sAdj[k * TM + i];
          int m1m = sAdj[(k + 1) * TM + i];
          float4 b0 = sBV[k], b1 = sBV[k + 1];
          float w0 = (a_i + b0.x >= 0.f) ? ea_i * b0.y : ea2_i * b0.z;
          w0 = (m0m > 0) ? w0 : 0.f;
          float w1 = (a_i + b1.x >= 0.f) ? ea_i * b1.y : ea2_i * b1.z;
          w1 = (m1m > 0) ? w1 : 0.f;
          zacc += w0; zacc += w1;
          cacc += (m0m > 0) ? 1.f : 0.f;
          cacc += (m1m > 0) ? 1.f : 0.f;
          unsigned ph;
          asm("cvt.rn.bf16x2.f32 %0, %1, %2;" : "=r"(ph) : "f"(w1), "f"(w0));
          float h0 = __uint_as_float(ph << 16);
          float h1 = __uint_as_float(ph & 0xffff0000u);
          unsigned pl;
          asm("cvt.rn.bf16x2.f32 %0, %1, %2;" : "=r"(pl) : "f"(w1 - h1), "f"(w0 - h0));
          ph4[jj] = ph; pl4[jj] = pl;
        }
        int off = (g * 16) ^ sx;
        *(uint4*)(phB + off) = make_uint4(ph4[0], ph4[1], ph4[2], ph4[3]);
        *(uint4*)(plB + off) = make_uint4(pl4[0], pl4[1], pl4[2], pl4[3]);
      }
      bar_arrive(b ? BFULL1 : BFULL0, 256);
      bar_sync(BPROD, 128);             // A[b]/BV[b] fully consumed by producers
      if (ch + 2 < NCHUNK)
        p_load(sm, b, ch + 2, adjG, cPak, XhT, XlT, i0, tp);
      cp_commit();                      // always one group per iteration
    }
    sZC[i]       = zacc;
    sZC[128 + i] = cacc;
  } else {
    // ================= CONSUMERS (warps 0-3) =================
    for (int u = t; u < 1024; u += 128)
      ((float4*)sW)[u] = ((const float4*)W)[u];

    const unsigned mBase = (unsigned)(wid * 32 + (lane & 15)) * 128;
    const unsigned aXor  = (lane & 7) << 4;
    const unsigned aCol  = (lane >> 4) << 4;
    unsigned dBase[4], dXor[4];
    {
      int dRow = ((lane >> 4) << 3) + (lane & 7);
      #pragma unroll
      for (int np = 0; np < 4; np++) {
        int d = np * 16 + dRow;
        dBase[np] = (unsigned)d * 128;
        dXor[np]  = (d & 7) << 4;
      }
    }
    const unsigned bCol = ((lane >> 3) & 1) << 4;

    for (int ch = 0; ch < NCHUNK; ch++) {
      const int b = ch & 1;
      bar_sync(b ? BFULL1 : BFULL0, 256);
      const unsigned pPh = smb + OFF_P + b * 32768;
      const unsigned pPl = pPh + 16384;
      const unsigned pXh = smb + OFF_X + (ch & 3) * 16384;
      const unsigned pXl = pXh + 8192;
      #pragma unroll
      for (int ks = 0; ks < 4; ks++) {
        unsigned ah0[4], ah1[4], al0[4], al1[4];
        unsigned aOff = ((unsigned)(ks * 32) + aCol) ^ aXor;
        ldsm4(ah0[0], ah0[1], ah0[2], ah0[3], pPh + mBase + aOff);
        ldsm4(ah1[0], ah1[1], ah1[2], ah1[3], pPh + mBase + 2048 + aOff);
        ldsm4(al0[0], al0[1], al0[2], al0[3], pPl + mBase + aOff);
        ldsm4(al1[0], al1[1], al1[2], al1[3], pPl + mBase + 2048 + aOff);
        #pragma unroll
        for (int np = 0; np < 4; np++) {
          unsigned bh[4], bl[4];
          unsigned bOff = ((unsigned)(ks * 32) + bCol) ^ dXor[np];
          ldsm4(bh[0], bh[1], bh[2], bh[3], pXh + dBase[np] + bOff);
          ldsm4(bl[0], bl[1], bl[2], bl[3], pXl + dBase[np] + bOff);
          mma16816(acc[0][2*np],   ah0, bh[0], bh[1]);
          mma16816(acc[0][2*np+1], ah0, bh[2], bh[3]);
          mma16816(acc[1][2*np],   ah1, bh[0], bh[1]);
          mma16816(acc[1][2*np+1], ah1, bh[2], bh[3]);
          mma16816(acc[0][2*np],   ah0, bl[0], bl[1]);
          mma16816(acc[0][2*np+1], ah0, bl[2], bl[3]);
          mma16816(acc[1][2*np],   ah1, bl[0], bl[1]);
          mma16816(acc[1][2*np+1], ah1, bl[2], bl[3]);
          mma16816(acc[0][2*np],   al0, bh[0], bh[1]);
          mma16816(acc[0][2*np+1], al0, bh[2], bh[3]);
          mma16816(acc[1][2*np],   al1, bh[0], bh[1]);
          mma16816(acc[1][2*np+1], al1, bh[2], bh[3]);
        }
      }
      bar_arrive(b ? BFREE1 : BFREE0, 256);
    }
  }

  __syncthreads();   // producers wrote sZC; consumers hold acc; A/P dead

  // ---- epilogue: consumers scatter normalized means into sM ----
  float* sM = (float*)(sm + OFF_M);
  if (t < 128) {
    #pragma unroll
    for (int mt = 0; mt < 2; mt++) {
      int base = wid * 32 + mt * 16 + (lane >> 2);
      int r0e = base, r1e = base + 8;
      float inv0 = 1.f / (sZC[r0e] * sZC[128 + r0e]);
      float inv1 = 1.f / (sZC[r1e] * sZC[128 + r1e]);
      #pragma unroll
      for (int nb = 0; nb < 8; nb++) {
        int c = nb * 8 + (lane & 3) * 2;
        sM[r0e * MSTRIDE + c]     = acc[mt][nb][0] * inv0;
        sM[r0e * MSTRIDE + c + 1] = acc[mt][nb][1] * inv0;
        sM[r1e * MSTRIDE + c]     = acc[mt][nb][2] * inv1;
        sM[r1e * MSTRIDE + c + 1] = acc[mt][nb][3] * inv1;
      }
    }
  }
  __syncthreads();

  // ---- projection through W + leaky + store (all 256 threads) ----
  const int tx = t & 7, ty = t >> 3;
  const int r0 = ty * 4, c0 = tx * 8;
  float o[4][8] = {};
  #pragma unroll 8
  for (int k = 0; k < 64; k++) {
    float mr[4];
    #pragma unroll
    for (int rr = 0; rr < 4; rr++) mr[rr] = sM[(r0 + rr) * MSTRIDE + k];
    float4 wa = *(const float4*)(sW + k * 64 + c0);
    float4 wb = *(const float4*)(sW + k * 64 + c0 + 4);
    float wv[8] = {wa.x, wa.y, wa.z, wa.w, wb.x, wb.y, wb.z, wb.w};
    #pragma unroll
    for (int rr = 0; rr < 4; rr++)
      #pragma unroll
      for (int cc = 0; cc < 8; cc++)
        o[rr][cc] = fmaf(mr[rr], wv[cc], o[rr][cc]);
  }
  #pragma unroll
  for (int rr = 0; rr < 4; rr++) {
    float v[8];
    #pragma unroll
    for (int cc = 0; cc < 8; cc++) {
      float x = o[rr][cc];
      v[cc] = (x >= 0.f) ? x : 0.01f * x;
    }
    float* op = out + (size_t)(i0 + r0 + rr) * 128 + side * 64 + c0;
    *(float4*)(op)     = make_float4(v[0], v[1], v[2], v[3]);
    *(float4*)(op + 4) = make_float4(v[4], v[5], v[6], v[7]);
  }
}

// ---------------------------------------------------------------------------
extern "C" void kernel_launch(void* const* d_in, const int* in_sizes, int n_in,
                              void* d_out, int out_size) {
  const float* nf  = (const float*)d_in[0];
  const float* ef  = (const float*)d_in[1];
  const int*   e2e = (const int*)  d_in[2];
  const int*   n2e = (const int*)  d_in[3];
  const float* Wn  = (const float*)d_in[4];
  const float* We  = (const float*)d_in[5];
  const float* pn  = (const float*)d_in[6];
  const float* pe  = (const float*)d_in[7];
  float* out = (float*)d_out;

  cudaFuncSetAttribute(agg_kernel, cudaFuncAttributeMaxDynamicSharedMemorySize, SMEM_BYTES);

  prep_kernel<<<EDIM / 64, 256>>>(nf, ef, Wn, We, pn, pe);
  dim3 grid(EDIM / TM, 1, 2);
  agg_kernel<<<grid, NTH, SMEM_BYTES>>>(e2e, n2e, Wn, We, out);
}